// round 5
// baseline (speedup 1.0000x reference)
#include <cuda_runtime.h>

// ---------------- problem constants ----------------
#define NLAT_I 240
#define NLON_I 480
#define NLAT_O 361
#define NLON_O 720
#define CI     32
#define CO     32
#define KK     7      // (NR-1)*NPHI+1
#define WOFF   10
#define WLAT   21

#define PI_F      3.14159265358979323846f
#define TWO_PI_F  6.28318530717958647692f
// CUTOFF = 3.25*pi/120 (double) rounded to float
#define CUTOFF_F  0.08508480103472356f
#define DR_F      0.028361600344907855f   // CUTOFF/3
#define DPH_F     2.0943951023931953f     // 2*pi/3

// ---------------- device scratch (no allocation allowed) ----------------
// xu stored pair-interleaved: [pair(16)][t(361)][p(720)][2]  (float2 per (pair,t,p))
static __device__ float g_xu2[16 * 361 * 720 * 2];           // 33.3 MB
// psi dense-addressed [k][t][d][pp], only support entries are written+read
static __device__ float g_psi[7 * 361 * 21 * 720];           // 152.8 MB
static __device__ float g_sp[7 * 361 * 21];                  // per-(k,t,d) scale partials
static __device__ float g_invsc[7 * 361];                    // 1/max(scale,1e-8)
static __device__ int   g_m[361 * 21];                       // support half-width per (t,d), -1 = empty

// ---------------- kernel A: bilinear upsample ----------------
__global__ void upsample_kernel(const float* __restrict__ x) {
    int idx = blockIdx.x * 256 + threadIdx.x;
    if (idx >= CI * NLAT_O * NLON_O) return;
    int p  = idx % NLON_O;
    int tt = (idx / NLON_O) % NLAT_O;
    int i  = idx / (NLON_O * NLAT_O);

    float theta = (float)tt * (PI_F / 360.0f);
    float post  = theta / (PI_F / 239.0f);
    float fi0 = floorf(post);
    int i0 = (int)fi0; i0 = min(max(i0, 0), NLAT_I - 1);
    int i1 = min(i0 + 1, NLAT_I - 1);
    float wt = post - (float)i0;

    float posp = ((float)p * (TWO_PI_F / (float)NLON_O)) / (TWO_PI_F / (float)NLON_I);
    float fj0 = floorf(posp);
    int j0 = ((int)fj0) % NLON_I;
    int j1 = j0 + 1; if (j1 >= NLON_I) j1 = 0;
    float wp = posp - fj0;

    const float* xi = x + i * (NLAT_I * NLON_I);
    float a  = xi[i0 * NLON_I + j0];
    float b  = xi[i0 * NLON_I + j1];
    float c  = xi[i1 * NLON_I + j0];
    float dv = xi[i1 * NLON_I + j1];
    float xl0 = (1.0f - wt) * a + wt * c;
    float xl1 = (1.0f - wt) * b + wt * dv;
    float val = (1.0f - wp) * xl0 + wp * xl1;

    g_xu2[(((i >> 1) * NLAT_O + tt) * NLON_O + p) * 2 + (i & 1)] = val;
}

// ---------------- kernel B: build psi (support-only) + scale partials + m ----------------
__global__ void build_psi_kernel() {
    int d = blockIdx.x;           // 0..20
    int t = blockIdx.y;           // 0..360
    int tid = threadIdx.x;

    int lt = t + d - WOFF;
    bool valid = (lt >= 0) && (lt <= NLAT_O - 1);
    int ltc = valid ? lt : (lt < 0 ? 0 : NLAT_O - 1);

    float tht = (float)t   * (PI_F / 360.0f);
    float thi = (float)ltc * (PI_F / 360.0f);
    float ca = cosf(tht), sa = sinf(tht);
    float cg = cosf(thi), sg = sinf(thi);
    float A = ca * cg;
    float B = sa * sg;
    float cosc = cosf(CUTOFF_F);

    int m;
    if (!valid)                 m = -1;
    else if (A - B >= cosc)     m = 360;          // full ring support
    else if (A + B <  cosc)     m = -1;           // empty
    else {
        float ratio = (cosc - A) / fmaxf(B, 1e-30f);
        ratio = fminf(fmaxf(ratio, -1.0f), 1.0f);
        m = (int)floorf(acosf(ratio) * (360.0f / PI_F)) + 2;  // +2 margin (psi->0 at boundary)
        if (m > 360) m = 360;
    }
    if (tid == 0) g_m[t * 21 + d] = m;

    float sums[7] = {0.f, 0.f, 0.f, 0.f, 0.f, 0.f, 0.f};
    if (m >= 0) {
        float qfac = sg * (PI_F / 360.0f) * (PI_F / 360.0f);
        int cnt = 2 * m + 1;
        for (int s = tid; s < cnt; s += 256) {
            int pp = s - m; if (pp < 0) pp += NLON_O;
            float beta = (float)pp * (TWO_PI_F / (float)NLON_O);
            float cb = cosf(beta), sb = sinf(beta);
            float z = A + cb * B;
            z = fminf(fmaxf(z, -1.0f), 1.0f);
            float r = acosf(z);
            float xx = ca * cb * sg - sa * cg;
            float yy = sb * sg;
            float phi = atan2f(yy, xx);
            if (phi < 0.0f) phi += TWO_PI_F;
            float mask = (r <= CUTOFF_F) ? qfac : 0.0f;

            float v[7];
            v[0] = fmaxf(0.0f, 1.0f - r * (1.0f / DR_F)) * mask;
            #pragma unroll
            for (int k = 1; k < 7; ++k) {
                int ir = (k - 1) / 3 + 1;
                int ip = (k - 1) % 3;
                float rad = fmaxf(0.0f, 1.0f - fabsf(r - (float)ir * DR_F) * (1.0f / DR_F));
                float dd  = fabsf(phi - (float)ip * DPH_F);
                dd = fminf(dd, TWO_PI_F - dd);
                float az = fmaxf(0.0f, 1.0f - dd * (1.0f / DPH_F));
                v[k] = rad * az * mask;
            }
            int base = (t * 21 + d) * NLON_O + pp;
            #pragma unroll
            for (int k = 0; k < 7; ++k) {
                g_psi[k * (361 * 21 * 720) + base] = v[k];
                sums[k] += v[k];
            }
        }
    }

    // deterministic block reduction -> partials
    __shared__ float red[8][7];
    int lane = tid & 31, w = tid >> 5;
    #pragma unroll
    for (int k = 0; k < 7; ++k) {
        float s = sums[k];
        #pragma unroll
        for (int o = 16; o > 0; o >>= 1) s += __shfl_down_sync(0xffffffffu, s, o);
        if (lane == 0) red[w][k] = s;
    }
    __syncthreads();
    if (tid < 7) {
        float s = 0.0f;
        #pragma unroll
        for (int ww = 0; ww < 8; ++ww) s += red[ww][tid];
        g_sp[(tid * 361 + t) * 21 + d] = s;
    }
}

// ---------------- kernel INV: deterministic scale sum + reciprocal ----------------
__global__ void inv_kernel() {
    int i = blockIdx.x * blockDim.x + threadIdx.x;
    if (i < 7 * 361) {
        float s = 0.0f;
        #pragma unroll
        for (int d = 0; d < 21; ++d) s += g_sp[i * 21 + d];
        g_invsc[i] = 1.0f / fmaxf(s, 1e-8f);
    }
}

// ---------------- kernel C: DISCO correlation + fused weight GEMM ----------------
// smem: phase1: xu window float2[16][720] (92160B) + psi float[7][728] (20384B) = 112544B
//       phase2 (aliased): z[224][32] (28672B) + w[32][224] (28672B)
#define SMEM_C (16 * 720 * 8 + 7 * 728 * 4)

__global__ void __launch_bounds__(256, 2)
conv_kernel(const float* __restrict__ wgt, float* __restrict__ y) {
    extern __shared__ float sm[];
    float2* xu_s  = (float2*)sm;                  // [16][720]
    float*  psi_s = sm + 16 * 720 * 2;            // [7][728]

    int ty = blockIdx.y;
    int t  = (ty & 1) ? (360 - (ty >> 1)) : (ty >> 1);   // heavy (polar) rows first
    int p0 = blockIdx.x * 32;
    int tid  = threadIdx.x;
    int lane = tid & 31;
    int ig   = tid >> 5;   // warp id = channel group (4 channels = 2 pairs)

    float invs[7];
    #pragma unroll
    for (int k = 0; k < 7; ++k) invs[k] = g_invsc[k * 361 + t];

    unsigned long long acc0[7], acc1[7];
    #pragma unroll
    for (int k = 0; k < 7; ++k) { acc0[k] = 0ull; acc1[k] = 0ull; }

    const float2* gx = (const float2*)g_xu2;

    for (int d = 0; d < 21; ++d) {
        int lt = t + d - WOFF;
        if (lt < 0 || lt > 360) continue;           // uniform across block
        int m = g_m[t * 21 + d];
        if (m < 0) continue;                        // uniform across block
        int cnt = 2 * m + 1;
        int L = 32 + 2 * m;
        int n = (L < 720) ? L : 720;
        int base = p0 - m;
        base %= 720; if (base < 0) base += 720;

        __syncthreads();
        // stage xu window: warp ig loads channel pairs 2ig, 2ig+1
        {
            int pr = 2 * ig;
            const float2* src0 = gx + (pr * NLAT_O + lt) * NLON_O;
            const float2* src1 = src0 + NLAT_O * NLON_O;
            for (int q = lane; q < n; q += 32) {
                int lon = base + q; if (lon >= 720) lon -= 720;
                xu_s[pr * 720 + q]       = src0[lon];
                xu_s[(pr + 1) * 720 + q] = src1[lon];
            }
        }
        // stage psi (fold 1/scale)
        int bp = 720 - m; if (m == 0) bp = 0;
        #pragma unroll
        for (int k = 0; k < 7; ++k) {
            const float sv = invs[k];
            const float* src = g_psi + (k * 361 + t) * (21 * 720) + d * 720;
            for (int s = tid; s < cnt; s += 256) {
                int pp = bp + s; if (pp >= 720) pp -= 720;
                psi_s[k * 728 + s] = src[pp] * sv;
            }
        }
        __syncthreads();

        const float2* xa = xu_s + (2 * ig) * 720;
        const float2* xb = xa + 720;
        int q = lane;
        for (int s = 0; s < cnt; ++s) {
            float2 xv0 = xa[q];
            float2 xv1 = xb[q];
            unsigned long long x0u, x1u;
            asm("mov.b64 %0, {%1,%2};" : "=l"(x0u) : "f"(xv0.x), "f"(xv0.y));
            asm("mov.b64 %0, {%1,%2};" : "=l"(x1u) : "f"(xv1.x), "f"(xv1.y));
            #pragma unroll
            for (int k = 0; k < 7; ++k) {
                float pv = psi_s[k * 728 + s];
                unsigned long long pu;
                asm("mov.b64 %0, {%1,%1};" : "=l"(pu) : "f"(pv));
                asm("fma.rn.f32x2 %0, %1, %2, %0;" : "+l"(acc0[k]) : "l"(pu), "l"(x0u));
                asm("fma.rn.f32x2 %0, %1, %2, %0;" : "+l"(acc1[k]) : "l"(pu), "l"(x1u));
            }
            ++q; if (q >= 720) q -= 720;
        }
    }

    __syncthreads();
    // phase 2: z -> smem, fused GEMM y = W z
    float* z_s = sm;               // [224][32]
    float* w_s = sm + 224 * 32;    // [32][224]
    #pragma unroll
    for (int k = 0; k < 7; ++k) {
        float a0x, a0y, a1x, a1y;
        asm("mov.b64 {%0,%1}, %2;" : "=f"(a0x), "=f"(a0y) : "l"(acc0[k]));
        asm("mov.b64 {%0,%1}, %2;" : "=f"(a1x), "=f"(a1y) : "l"(acc1[k]));
        int kb = k * 32;
        z_s[(kb + 4 * ig + 0) * 32 + lane] = a0x;
        z_s[(kb + 4 * ig + 1) * 32 + lane] = a0y;
        z_s[(kb + 4 * ig + 2) * 32 + lane] = a1x;
        z_s[(kb + 4 * ig + 3) * 32 + lane] = a1y;
    }
    for (int idx = tid; idx < CO * 224; idx += 256) {
        int o = idx / 224;
        int r = idx - o * 224;
        int k = r >> 5;
        int i = r & 31;
        w_s[idx] = wgt[(o * CI + i) * KK + k];
    }
    __syncthreads();

    int p = p0 + lane;
    if (p < 720) {
        #pragma unroll
        for (int oo = 0; oo < 4; ++oo) {
            int o = ig + oo * 8;
            const float* wr = w_s + o * 224;
            float sum = 0.0f;
            #pragma unroll 8
            for (int ki = 0; ki < 224; ++ki)
                sum = fmaf(wr[ki], z_s[ki * 32 + lane], sum);
            y[(o * NLAT_O + t) * NLON_O + p] = sum;
        }
    }
}

// ---------------- launcher ----------------
extern "C" void kernel_launch(void* const* d_in, const int* in_sizes, int n_in,
                              void* d_out, int out_size) {
    const float* x = (const float*)d_in[0];       // [1,32,240,480]
    const float* w = (const float*)d_in[1];       // [32,32,7]
    float* y = (float*)d_out;                     // [1,32,361,720]

    cudaFuncSetAttribute(conv_kernel, cudaFuncAttributeMaxDynamicSharedMemorySize, SMEM_C);

    int nA = CI * NLAT_O * NLON_O;
    upsample_kernel<<<(nA + 255) / 256, 256>>>(x);
    build_psi_kernel<<<dim3(21, 361), 256>>>();
    inv_kernel<<<(7 * 361 + 255) / 256, 256>>>();
    conv_kernel<<<dim3(23, 361), 256, SMEM_C>>>(w, y);
}

// round 6
// speedup vs baseline: 1.4495x; 1.4495x over previous
#include <cuda_runtime.h>

#define NLAT_I 240
#define NLON_I 480
#define NLAT_O 361
#define NLON_O 720
#define CI     32
#define CO     32
#define KK     7
#define WOFF   10

#define PI_F      3.14159265358979323846f
#define TWO_PI_F  6.28318530717958647692f
#define CUTOFF_F  0.08508480103472356f
#define DR_F      0.028361600344907855f
#define DPH_F     2.0943951023931953f

typedef unsigned long long u64;

// ---------------- device scratch ----------------
static __device__ float g_xu2[16 * 361 * 720 * 2];                 // xu pair-interleaved
static __device__ float g_psi8[(size_t)361 * 21 * 728 * 8];        // packed psi rows
static __device__ float g_sp[7 * 361 * 21];
static __device__ float g_invsc[7 * 361];
static __device__ int   g_m[361 * 21];
static __device__ int   g_m2[361 * 21];

// ---------------- kernel A: bilinear upsample ----------------
__global__ void upsample_kernel(const float* __restrict__ x) {
    int idx = blockIdx.x * 256 + threadIdx.x;
    if (idx >= CI * NLAT_O * NLON_O) return;
    int p  = idx % NLON_O;
    int tt = (idx / NLON_O) % NLAT_O;
    int i  = idx / (NLON_O * NLAT_O);

    float theta = (float)tt * (PI_F / 360.0f);
    float post  = theta / (PI_F / 239.0f);
    float fi0 = floorf(post);
    int i0 = (int)fi0; i0 = min(max(i0, 0), NLAT_I - 1);
    int i1 = min(i0 + 1, NLAT_I - 1);
    float wt = post - (float)i0;

    float posp = ((float)p * (TWO_PI_F / (float)NLON_O)) / (TWO_PI_F / (float)NLON_I);
    float fj0 = floorf(posp);
    int j0 = ((int)fj0) % NLON_I;
    int j1 = j0 + 1; if (j1 >= NLON_I) j1 = 0;
    float wp = posp - fj0;

    const float* xi = x + i * (NLAT_I * NLON_I);
    float a  = xi[i0 * NLON_I + j0];
    float b  = xi[i0 * NLON_I + j1];
    float c  = xi[i1 * NLON_I + j0];
    float dv = xi[i1 * NLON_I + j1];
    float xl0 = (1.0f - wt) * a + wt * c;
    float xl1 = (1.0f - wt) * b + wt * dv;
    float val = (1.0f - wp) * xl0 + wp * xl1;

    g_xu2[(((i >> 1) * NLAT_O + tt) * NLON_O + p) * 2 + (i & 1)] = val;
}

// ---------------- kernel B: build packed psi + bounds ----------------
__global__ void build_psi_kernel() {
    int d = blockIdx.x;           // 0..20
    int t = blockIdx.y;           // 0..360
    int tid = threadIdx.x;

    int lt = t + d - WOFF;
    bool valid = (lt >= 0) && (lt <= NLAT_O - 1);
    int ltc = min(max(lt, 0), NLAT_O - 1);

    float tht = (float)t   * (PI_F / 360.0f);
    float thi = (float)ltc * (PI_F / 360.0f);
    float ca = cosf(tht), sa = sinf(tht);
    float cg = cosf(thi), sg = sinf(thi);
    float A = ca * cg;
    float B = sa * sg;
    float cosc = cosf(CUTOFF_F);

    int m;
    if (!valid)                 m = -1;
    else if (A - B >= cosc)     m = 360;
    else if (A + B <  cosc)     m = -1;
    else {
        float ratio = (cosc - A) / fmaxf(B, 1e-30f);
        ratio = fminf(fmaxf(ratio, -1.0f), 1.0f);
        m = (int)floorf(acosf(ratio) * (360.0f / PI_F)) + 2;
        if (m > 360) m = 360;
    }

    // inner half-width (r <= 2dr region) with conservative margins
    float cosc2i = cosf(2.0f * DR_F);
    float cosc2o = cosf(2.0f * DR_F + 1e-4f);
    int m2;
    if (m < 0)                   m2 = -1;
    else if (A - B >= cosc2i)    m2 = 360;
    else if (A + B <  cosc2o)    m2 = -1;
    else {
        float ratio = (cosc2o - A) / fmaxf(B, 1e-30f);
        ratio = fminf(fmaxf(ratio, -1.0f), 1.0f);
        m2 = (int)floorf(acosf(ratio) * (360.0f / PI_F)) + 3;
        if (m2 > 360) m2 = 360;
    }
    if (tid == 0) { g_m[t * 21 + d] = m; g_m2[t * 21 + d] = m2; }

    // haversine constants (well-conditioned r for values)
    float dth = (float)(ltc - t) * (PI_F / 360.0f);
    float shd = sinf(0.5f * dth);
    float hav_lat = shd * shd;

    float sums[7] = {0.f, 0.f, 0.f, 0.f, 0.f, 0.f, 0.f};
    if (m >= 0) {
        float qfac = sg * (PI_F / 360.0f) * (PI_F / 360.0f);
        int cnt = 2 * m + 1;
        for (int s = tid; s < cnt; s += 256) {
            int pp = s - m; if (pp < 0) pp += NLON_O;
            float beta = (float)pp * (TWO_PI_F / (float)NLON_O);
            float cb = cosf(beta), sb = sinf(beta);
            // mask: same acos-z formulation as reference
            float z = A + cb * B;
            z = fminf(fmaxf(z, -1.0f), 1.0f);
            float r_acos = acosf(z);
            float mask = (r_acos <= CUTOFF_F) ? qfac : 0.0f;
            // accurate r via haversine
            float sbh = sinf(0.5f * beta);
            float h = hav_lat + B * sbh * sbh;
            float r = 2.0f * asinf(fminf(sqrtf(fmaxf(h, 0.0f)), 1.0f));

            float xx = ca * cb * sg - sa * cg;
            float yy = sb * sg;
            float phi = atan2f(yy, xx);
            if (phi < 0.0f) phi += TWO_PI_F;

            float v[7];
            v[0] = fmaxf(0.0f, 1.0f - r * (1.0f / DR_F)) * mask;
            #pragma unroll
            for (int k = 1; k < 7; ++k) {
                int ir = (k - 1) / 3 + 1;
                int ip = (k - 1) % 3;
                float rad = fmaxf(0.0f, 1.0f - fabsf(r - (float)ir * DR_F) * (1.0f / DR_F));
                float dd  = fabsf(phi - (float)ip * DPH_F);
                dd = fminf(dd, TWO_PI_F - dd);
                float az = fmaxf(0.0f, 1.0f - dd * (1.0f / DPH_F));
                v[k] = rad * az * mask;
            }
            size_t b8 = ((size_t)(t * 21 + d) * 728 + s) * 8;
            g_psi8[b8 + 0] = v[4];
            g_psi8[b8 + 1] = v[5];
            g_psi8[b8 + 2] = v[6];
            g_psi8[b8 + 3] = 0.0f;
            g_psi8[b8 + 4] = v[0];
            g_psi8[b8 + 5] = v[1];
            g_psi8[b8 + 6] = v[2];
            g_psi8[b8 + 7] = v[3];
            #pragma unroll
            for (int k = 0; k < 7; ++k) sums[k] += v[k];
        }
    }

    __shared__ float red[8][7];
    int lane = tid & 31, w = tid >> 5;
    #pragma unroll
    for (int k = 0; k < 7; ++k) {
        float s = sums[k];
        #pragma unroll
        for (int o = 16; o > 0; o >>= 1) s += __shfl_down_sync(0xffffffffu, s, o);
        if (lane == 0) red[w][k] = s;
    }
    __syncthreads();
    if (tid < 7) {
        float s = 0.0f;
        #pragma unroll
        for (int ww = 0; ww < 8; ++ww) s += red[ww][tid];
        g_sp[(tid * 361 + t) * 21 + d] = s;
    }
}

// ---------------- kernel INV ----------------
__global__ void inv_kernel() {
    int i = blockIdx.x * blockDim.x + threadIdx.x;
    if (i < 7 * 361) {
        float s = 0.0f;
        #pragma unroll
        for (int d = 0; d < 21; ++d) s += g_sp[i * 21 + d];
        g_invsc[i] = 1.0f / fmaxf(s, 1e-8f);
    }
}

// ---------------- kernel C: conv + fused GEMM ----------------
// phase1 smem: xu float2[16][720] (92160B) + psi float[728][8] (23296B) = 115456B
// phase2 (aliased): z2 float[112][32][2] (28672B) + w2 float2[32][112] (28672B)
#define SMEM_C (16 * 720 * 8 + 728 * 8 * 4)

__global__ void __launch_bounds__(256, 2)
conv_kernel(const float* __restrict__ wgt, float* __restrict__ y) {
    extern __shared__ float sm[];
    float2* xu_s  = (float2*)sm;                        // [16][720]
    float*  psi_s = sm + 16 * 720 * 2;                  // [728][8]
    unsigned psi_u = (unsigned)__cvta_generic_to_shared(psi_s);

    int ty = blockIdx.y;
    int t  = (ty & 1) ? (360 - (ty >> 1)) : (ty >> 1);  // heavy rows first
    int p0 = blockIdx.x * 32;
    int tid  = threadIdx.x;
    int lane = tid & 31;
    int ig   = tid >> 5;                                // warp -> channels 4ig..4ig+3

    float invs[8];
    #pragma unroll
    for (int k = 0; k < 7; ++k) invs[k] = g_invsc[k * 361 + t];
    invs[7] = 0.0f;

    u64 aA[4], aB[4], aC[4], aD[4];
    #pragma unroll
    for (int c = 0; c < 4; ++c) { aA[c] = 0ull; aB[c] = 0ull; aC[c] = 0ull; aD[c] = 0ull; }

    const float2* gx = (const float2*)g_xu2;

    for (int d = 0; d < 21; ++d) {
        int lt = t + d - WOFF;
        if (lt < 0 || lt > 360) continue;
        int m = g_m[t * 21 + d];
        if (m < 0) continue;
        int m2 = g_m2[t * 21 + d];
        int cnt = 2 * m + 1;
        int L = 32 + 2 * m;
        int n = (L < 720) ? L : 720;
        int base = p0 - m;
        base %= 720; if (base < 0) base += 720;
        int iA, iB;
        if (m2 < 0) { iA = cnt; iB = cnt; }
        else { iA = max(0, m - m2); iB = min(cnt, m + m2 + 1); }

        __syncthreads();
        // stage xu window (warp ig -> pairs 2ig, 2ig+1)
        {
            int pr = 2 * ig;
            const float2* src0 = gx + (pr * NLAT_O + lt) * NLON_O;
            const float2* src1 = src0 + NLAT_O * NLON_O;
            for (int q = lane; q < n; q += 32) {
                int lon = base + q; if (lon >= 720) lon -= 720;
                xu_s[pr * 720 + q]       = src0[lon];
                xu_s[(pr + 1) * 720 + q] = src1[lon];
            }
        }
        // stage psi (streaming, fold inv scale)
        {
            const float4* src = (const float4*)(g_psi8 + ((size_t)(t * 21 + d)) * 728 * 8);
            float4* dst = (float4*)psi_s;
            for (int s = tid; s < cnt; s += 256) {
                float4 a = src[s * 2 + 0];
                float4 b = src[s * 2 + 1];
                a.x *= invs[4]; a.y *= invs[5]; a.z *= invs[6]; a.w = 0.0f;
                b.x *= invs[0]; b.y *= invs[1]; b.z *= invs[2]; b.w *= invs[3];
                dst[s * 2 + 0] = a;
                dst[s * 2 + 1] = b;
            }
        }
        __syncthreads();

        const float2* xa = xu_s + (2 * ig) * 720;
        const float2* xb = xa + 720;
        int q = lane;
        int s = 0;
        // outer-left: only pairs (k4,k5),(k6,0)
        for (; s < iA; ++s) {
            float2 xv0 = xa[q];
            float2 xv1 = xb[q];
            u64 dup[4];
            asm("mov.b64 %0,{%1,%1};" : "=l"(dup[0]) : "f"(xv0.x));
            asm("mov.b64 %0,{%1,%1};" : "=l"(dup[1]) : "f"(xv0.y));
            asm("mov.b64 %0,{%1,%1};" : "=l"(dup[2]) : "f"(xv1.x));
            asm("mov.b64 %0,{%1,%1};" : "=l"(dup[3]) : "f"(xv1.y));
            u64 pA, pB;
            asm("ld.shared.v2.u64 {%0,%1},[%2];" : "=l"(pA), "=l"(pB) : "r"(psi_u + (unsigned)s * 32u));
            #pragma unroll
            for (int c = 0; c < 4; ++c) {
                asm("fma.rn.f32x2 %0,%1,%2,%0;" : "+l"(aA[c]) : "l"(pA), "l"(dup[c]));
                asm("fma.rn.f32x2 %0,%1,%2,%0;" : "+l"(aB[c]) : "l"(pB), "l"(dup[c]));
            }
            ++q; if (q >= 720) q -= 720;
        }
        // inner: all 4 pairs
        for (; s < iB; ++s) {
            float2 xv0 = xa[q];
            float2 xv1 = xb[q];
            u64 dup[4];
            asm("mov.b64 %0,{%1,%1};" : "=l"(dup[0]) : "f"(xv0.x));
            asm("mov.b64 %0,{%1,%1};" : "=l"(dup[1]) : "f"(xv0.y));
            asm("mov.b64 %0,{%1,%1};" : "=l"(dup[2]) : "f"(xv1.x));
            asm("mov.b64 %0,{%1,%1};" : "=l"(dup[3]) : "f"(xv1.y));
            u64 pA, pB, pC, pD;
            asm("ld.shared.v2.u64 {%0,%1},[%2];" : "=l"(pA), "=l"(pB) : "r"(psi_u + (unsigned)s * 32u));
            asm("ld.shared.v2.u64 {%0,%1},[%2];" : "=l"(pC), "=l"(pD) : "r"(psi_u + (unsigned)s * 32u + 16u));
            #pragma unroll
            for (int c = 0; c < 4; ++c) {
                asm("fma.rn.f32x2 %0,%1,%2,%0;" : "+l"(aA[c]) : "l"(pA), "l"(dup[c]));
                asm("fma.rn.f32x2 %0,%1,%2,%0;" : "+l"(aB[c]) : "l"(pB), "l"(dup[c]));
                asm("fma.rn.f32x2 %0,%1,%2,%0;" : "+l"(aC[c]) : "l"(pC), "l"(dup[c]));
                asm("fma.rn.f32x2 %0,%1,%2,%0;" : "+l"(aD[c]) : "l"(pD), "l"(dup[c]));
            }
            ++q; if (q >= 720) q -= 720;
        }
        // outer-right
        for (; s < cnt; ++s) {
            float2 xv0 = xa[q];
            float2 xv1 = xb[q];
            u64 dup[4];
            asm("mov.b64 %0,{%1,%1};" : "=l"(dup[0]) : "f"(xv0.x));
            asm("mov.b64 %0,{%1,%1};" : "=l"(dup[1]) : "f"(xv0.y));
            asm("mov.b64 %0,{%1,%1};" : "=l"(dup[2]) : "f"(xv1.x));
            asm("mov.b64 %0,{%1,%1};" : "=l"(dup[3]) : "f"(xv1.y));
            u64 pA, pB;
            asm("ld.shared.v2.u64 {%0,%1},[%2];" : "=l"(pA), "=l"(pB) : "r"(psi_u + (unsigned)s * 32u));
            #pragma unroll
            for (int c = 0; c < 4; ++c) {
                asm("fma.rn.f32x2 %0,%1,%2,%0;" : "+l"(aA[c]) : "l"(pA), "l"(dup[c]));
                asm("fma.rn.f32x2 %0,%1,%2,%0;" : "+l"(aB[c]) : "l"(pB), "l"(dup[c]));
            }
            ++q; if (q >= 720) q -= 720;
        }
    }

    __syncthreads();
    // ---- phase 2: z2 [112 kpair][32 lane][2], w2 [32 o][112 kpair] (float2 dup of i-pair)
    float*  z2f = sm;                       // 7168 floats
    float2* w2  = (float2*)(sm + 7168);     // 3584 float2

    // scatter accumulators: acc pair -> (kA,kB) values for channel i
    {
        int ibase = 4 * ig;
        #pragma unroll
        for (int c = 0; c < 4; ++c) {
            int i = ibase + c;
            int half = i >> 1, par = i & 1;
            float lo, hi;
            // aA -> k4,k5
            asm("mov.b64 {%0,%1},%2;" : "=f"(lo), "=f"(hi) : "l"(aA[c]));
            z2f[(((4 * 16 + half) * 32 + lane) * 2) + par] = lo;
            z2f[(((5 * 16 + half) * 32 + lane) * 2) + par] = hi;
            // aB -> k6
            asm("mov.b64 {%0,%1},%2;" : "=f"(lo), "=f"(hi) : "l"(aB[c]));
            z2f[(((6 * 16 + half) * 32 + lane) * 2) + par] = lo;
            // aC -> k0,k1
            asm("mov.b64 {%0,%1},%2;" : "=f"(lo), "=f"(hi) : "l"(aC[c]));
            z2f[(((0 * 16 + half) * 32 + lane) * 2) + par] = lo;
            z2f[(((1 * 16 + half) * 32 + lane) * 2) + par] = hi;
            // aD -> k2,k3
            asm("mov.b64 {%0,%1},%2;" : "=f"(lo), "=f"(hi) : "l"(aD[c]));
            z2f[(((2 * 16 + half) * 32 + lane) * 2) + par] = lo;
            z2f[(((3 * 16 + half) * 32 + lane) * 2) + par] = hi;
        }
    }
    // stage w pairs
    for (int idx = tid; idx < CO * 112; idx += 256) {
        int o = idx / 112;
        int j = idx - o * 112;
        int k  = j >> 4;
        int i0 = (j & 15) * 2;
        w2[o * 112 + j] = make_float2(wgt[(o * CI + i0) * KK + k],
                                      wgt[(o * CI + i0 + 1) * KK + k]);
    }
    __syncthreads();

    const u64* z2u = (const u64*)z2f;
    const u64* w2u = (const u64*)w2;
    u64 acc2[4];
    #pragma unroll
    for (int oo = 0; oo < 4; ++oo) acc2[oo] = 0ull;

    #pragma unroll 4
    for (int j = 0; j < 112; ++j) {
        u64 zp = z2u[j * 32 + lane];
        #pragma unroll
        for (int oo = 0; oo < 4; ++oo) {
            u64 wv = w2u[(ig + 8 * oo) * 112 + j];
            asm("fma.rn.f32x2 %0,%1,%2,%0;" : "+l"(acc2[oo]) : "l"(wv), "l"(zp));
        }
    }

    int p = p0 + lane;
    if (p < 720) {
        #pragma unroll
        for (int oo = 0; oo < 4; ++oo) {
            int o = ig + 8 * oo;
            float lo, hi;
            asm("mov.b64 {%0,%1},%2;" : "=f"(lo), "=f"(hi) : "l"(acc2[oo]));
            y[((size_t)o * NLAT_O + t) * NLON_O + p] = lo + hi;
        }
    }
}

// ---------------- launcher ----------------
extern "C" void kernel_launch(void* const* d_in, const int* in_sizes, int n_in,
                              void* d_out, int out_size) {
    const float* x = (const float*)d_in[0];       // [1,32,240,480]
    const float* w = (const float*)d_in[1];       // [32,32,7]
    float* y = (float*)d_out;                     // [1,32,361,720]

    cudaFuncSetAttribute(conv_kernel, cudaFuncAttributeMaxDynamicSharedMemorySize, SMEM_C);

    int nA = CI * NLAT_O * NLON_O;
    upsample_kernel<<<(nA + 255) / 256, 256>>>(x);
    build_psi_kernel<<<dim3(21, 361), 256>>>();
    inv_kernel<<<(7 * 361 + 255) / 256, 256>>>();
    conv_kernel<<<dim3(23, 361), 256, SMEM_C>>>(w, y);
}